// round 8
// baseline (speedup 1.0000x reference)
#include <cuda_runtime.h>
#include <cstdint>

// Problem constants
constexpr int NN   = 100000;   // nodes
constexpr int EE   = 1600000;  // edges
constexpr int IND  = 256;
constexpr int HIDD = 128;
constexpr int OUTD = 32;

// Scratch (static device arrays; no allocation allowed)
__device__ int   g_is32;           // 1 if edge_index is int32, 0 if int64
__device__ float g_deg[NN];        // weighted degree (with self-loop)
__device__ int   g_cnt[NN];        // in-edge count per dst (no self-loop)
__device__ int   g_off[NN];        // CSR row offsets (exclusive prefix of cnt)
__device__ int   g_cur[NN];        // fill cursors
__device__ float g_inv[NN];        // deg^{-1/2}
__device__ int   g_esrc[EE];       // CSR: source node per slot
__device__ float g_enorm[EE];      // CSR: edge norm per slot
__device__ float g_h1[(size_t)NN * HIDD];   // x @ W1
__device__ float g_h2[(size_t)NN * OUTD];   // relu(x_emb) @ W2

// ---------------------------------------------------------------------------
// dtype probe: true int64 edge_index values all lie in [0, NN); int32 data
// read as int64 fuses two indices -> huge values. 16 probes => misdetect ~0.
// ---------------------------------------------------------------------------
__global__ void k_probe(const long long* __restrict__ ei) {
    if (threadIdx.x == 0 && blockIdx.x == 0) {
        int ok = 1;
        for (int i = 0; i < 16; i++) {
            long long v = ei[i];
            if (v < 0 || v >= NN) { ok = 0; break; }
        }
        g_is32 = ok ? 0 : 1;
    }
}

__device__ __forceinline__ int load_idx(const long long* ei, size_t pos, int is32) {
    return is32 ? ((const int*)ei)[pos] : (int)ei[pos];
}

// ---------------------------------------------------------------------------
// init: zero counts, deg = 1 (self-loop weight)
// ---------------------------------------------------------------------------
__global__ void k_init() {
    int i = blockIdx.x * blockDim.x + threadIdx.x;
    if (i < NN) { g_deg[i] = 1.0f; g_cnt[i] = 0; }
}

// weighted degree + in-edge counts (scalar atomics only, guarded indices)
__global__ void k_deg(const long long* __restrict__ ei, const float* __restrict__ ew) {
    int e = blockIdx.x * blockDim.x + threadIdx.x;
    if (e < EE) {
        int is32 = g_is32;
        int d = load_idx(ei, (size_t)EE + e, is32);
        if ((unsigned)d < (unsigned)NN) {
            atomicAdd(&g_deg[d], ew[e]);
            atomicAdd(&g_cnt[d], 1);
        }
    }
}

__global__ void k_inv() {
    int i = blockIdx.x * blockDim.x + threadIdx.x;
    if (i < NN) {
        float d = g_deg[i];
        g_inv[i] = d > 0.0f ? rsqrtf(fmaxf(d, 1e-12f)) : 0.0f;
    }
}

// single-block exclusive scan of g_cnt -> g_off (and cursor copy)
__global__ void k_scan() {
    __shared__ int sums[1024];
    const int T  = 1024;
    const int CH = (NN + T - 1) / T;      // 98
    int t  = threadIdx.x;
    int lo = t * CH;
    int hi = lo + CH < NN ? lo + CH : NN;
    int s = 0;
    for (int i = lo; i < hi; i++) s += g_cnt[i];
    sums[t] = s;
    __syncthreads();
    if (t == 0) {
        int run = 0;
        for (int i = 0; i < T; i++) { int v = sums[i]; sums[i] = run; run += v; }
    }
    __syncthreads();
    int run = sums[t];
    for (int i = lo; i < hi; i++) {
        g_off[i] = run;
        g_cur[i] = run;
        run += g_cnt[i];
    }
}

// scatter edges into CSR slots; compute norm on the fly (guarded indices)
__global__ void k_fill(const long long* __restrict__ ei, const float* __restrict__ ew) {
    int e = blockIdx.x * blockDim.x + threadIdx.x;
    if (e < EE) {
        int is32 = g_is32;
        int s = load_idx(ei, (size_t)e, is32);
        int d = load_idx(ei, (size_t)EE + e, is32);
        if ((unsigned)s < (unsigned)NN && (unsigned)d < (unsigned)NN) {
            int pos = atomicAdd(&g_cur[d], 1);
            g_esrc[pos]  = s;
            g_enorm[pos] = g_inv[s] * ew[e] * g_inv[d];
        }
    }
}

// ---------------------------------------------------------------------------
// Tiled fp32 GEMM: H[M, ND] = op(X)[M, KK] @ W[KK, ND]
// block: 256 threads, tile 64 rows x ND cols, thread grid 16x16, micro 4 x TN
// DSTBUF: 1 -> g_h1, 2 -> g_h2
// ---------------------------------------------------------------------------
template <int KK, int ND, int TN, bool RELU, int DSTBUF>
__global__ void k_gemm(const float* __restrict__ X, const float* __restrict__ W) {
    float* __restrict__ H = (DSTBUF == 1) ? g_h1 : g_h2;

    constexpr int KT = 32;
    __shared__ __align__(16) float As[KT][68];   // [k][row], 64 rows + pad
    __shared__ __align__(16) float Bs[KT][ND];

    int tid  = threadIdx.x;
    int ty   = tid >> 4;        // 0..15 -> row group (4 rows each)
    int tx   = tid & 15;        // 0..15 -> col group (TN cols each)
    int row0 = blockIdx.x * 64;

    float acc[4][TN];
#pragma unroll
    for (int i = 0; i < 4; i++)
#pragma unroll
        for (int j = 0; j < TN; j++) acc[i][j] = 0.0f;

    for (int k0 = 0; k0 < KK; k0 += KT) {
#pragma unroll
        for (int i = tid; i < 64 * KT / 4; i += 256) {
            int r  = i >> 3;
            int kk = (i & 7) << 2;
            int gr = row0 + r;
            float4 v = make_float4(0.f, 0.f, 0.f, 0.f);
            if (gr < NN) v = *(const float4*)(X + (size_t)gr * KK + k0 + kk);
            if (RELU) {
                v.x = fmaxf(v.x, 0.f); v.y = fmaxf(v.y, 0.f);
                v.z = fmaxf(v.z, 0.f); v.w = fmaxf(v.w, 0.f);
            }
            As[kk + 0][r] = v.x; As[kk + 1][r] = v.y;
            As[kk + 2][r] = v.z; As[kk + 3][r] = v.w;
        }
#pragma unroll
        for (int i = tid; i < KT * ND / 4; i += 256) {
            int kk = i / (ND / 4);
            int cc = (i % (ND / 4)) * 4;
            *(float4*)(&Bs[kk][cc]) = *(const float4*)(W + (size_t)(k0 + kk) * ND + cc);
        }
        __syncthreads();

#pragma unroll
        for (int k = 0; k < KT; k++) {
            float4 a = *(const float4*)(&As[k][ty * 4]);
            float av[4] = {a.x, a.y, a.z, a.w};
            float b[TN];
#pragma unroll
            for (int j = 0; j < TN; j++) b[j] = Bs[k][tx * TN + j];
#pragma unroll
            for (int i = 0; i < 4; i++)
#pragma unroll
                for (int j = 0; j < TN; j++) acc[i][j] += av[i] * b[j];
        }
        __syncthreads();
    }

#pragma unroll
    for (int i = 0; i < 4; i++) {
        int gr = row0 + ty * 4 + i;
        if (gr < NN) {
#pragma unroll
            for (int j = 0; j < TN; j++)
                H[(size_t)gr * ND + tx * TN + j] = acc[i][j];
        }
    }
}

// ---------------------------------------------------------------------------
// CSR aggregation, layer 1: one warp per node, lane owns a float4 chunk.
// out = sum_{e in in(n)} norm_e * h1[src_e] + inv(n)^2 * h1[n] + b1
// Pure gathers + one store; no atomics. Edge loop unrolled x4 for MLP.
// ---------------------------------------------------------------------------
__global__ void k_agg1(float* __restrict__ xemb, const float* __restrict__ b1) {
    int warp = (blockIdx.x * blockDim.x + threadIdx.x) >> 5;
    int lane = threadIdx.x & 31;
    if (warp >= NN) return;

    int beg = g_off[warp];
    int cnt = g_cnt[warp];
    float iv = g_inv[warp];
    float inv2 = iv * iv;

    size_t off = (size_t)warp * HIDD + lane * 4;
    float4 h = *(const float4*)(g_h1 + off);
    float4 b = *(const float4*)(b1 + lane * 4);
    float4 acc;
    acc.x = inv2 * h.x + b.x;
    acc.y = inv2 * h.y + b.y;
    acc.z = inv2 * h.z + b.z;
    acc.w = inv2 * h.w + b.w;

    int i = 0;
    for (; i + 4 <= cnt; i += 4) {
        int   s0 = g_esrc[beg + i + 0], s1 = g_esrc[beg + i + 1];
        int   s2 = g_esrc[beg + i + 2], s3 = g_esrc[beg + i + 3];
        float n0 = g_enorm[beg + i + 0], n1 = g_enorm[beg + i + 1];
        float n2 = g_enorm[beg + i + 2], n3 = g_enorm[beg + i + 3];
        float4 v0 = *(const float4*)(g_h1 + (size_t)s0 * HIDD + lane * 4);
        float4 v1 = *(const float4*)(g_h1 + (size_t)s1 * HIDD + lane * 4);
        float4 v2 = *(const float4*)(g_h1 + (size_t)s2 * HIDD + lane * 4);
        float4 v3 = *(const float4*)(g_h1 + (size_t)s3 * HIDD + lane * 4);
        acc.x += n0 * v0.x + n1 * v1.x + n2 * v2.x + n3 * v3.x;
        acc.y += n0 * v0.y + n1 * v1.y + n2 * v2.y + n3 * v3.y;
        acc.z += n0 * v0.z + n1 * v1.z + n2 * v2.z + n3 * v3.z;
        acc.w += n0 * v0.w + n1 * v1.w + n2 * v2.w + n3 * v3.w;
    }
    for (; i < cnt; i++) {
        int   s  = g_esrc[beg + i];
        float nw = g_enorm[beg + i];
        float4 v = *(const float4*)(g_h1 + (size_t)s * HIDD + lane * 4);
        acc.x += nw * v.x; acc.y += nw * v.y;
        acc.z += nw * v.z; acc.w += nw * v.w;
    }
    *(float4*)(xemb + off) = acc;
}

// layer 2: 32 features -> one float per lane
__global__ void k_agg2(float* __restrict__ outp, const float* __restrict__ b2) {
    int warp = (blockIdx.x * blockDim.x + threadIdx.x) >> 5;
    int lane = threadIdx.x & 31;
    if (warp >= NN) return;

    int beg = g_off[warp];
    int cnt = g_cnt[warp];
    float iv = g_inv[warp];
    float inv2 = iv * iv;

    size_t off = (size_t)warp * OUTD + lane;
    float acc = inv2 * g_h2[off] + b2[lane];

    int i = 0;
    for (; i + 4 <= cnt; i += 4) {
        int   s0 = g_esrc[beg + i + 0], s1 = g_esrc[beg + i + 1];
        int   s2 = g_esrc[beg + i + 2], s3 = g_esrc[beg + i + 3];
        float n0 = g_enorm[beg + i + 0], n1 = g_enorm[beg + i + 1];
        float n2 = g_enorm[beg + i + 2], n3 = g_enorm[beg + i + 3];
        acc += n0 * g_h2[(size_t)s0 * OUTD + lane]
             + n1 * g_h2[(size_t)s1 * OUTD + lane]
             + n2 * g_h2[(size_t)s2 * OUTD + lane]
             + n3 * g_h2[(size_t)s3 * OUTD + lane];
    }
    for (; i < cnt; i++)
        acc += g_enorm[beg + i] * g_h2[(size_t)g_esrc[beg + i] * OUTD + lane];
    outp[off] = acc;
}

// ---------------------------------------------------------------------------
extern "C" void kernel_launch(void* const* d_in, const int* in_sizes, int n_in,
                              void* d_out, int out_size) {
    const float*     x  = (const float*)d_in[0];
    const long long* ei = (const long long*)d_in[1];   // int32 or int64 — probed
    const float*     ew = (const float*)d_in[2];
    const float*     W1 = (const float*)d_in[3];
    const float*     b1 = (const float*)d_in[4];
    const float*     W2 = (const float*)d_in[5];
    const float*     b2 = (const float*)d_in[6];

    float* outp = (float*)d_out;                       // [NN, OUTD]
    float* xemb = outp + (size_t)NN * OUTD;            // [NN, HIDD]

    const int TB = 256;
    // edge dtype probe + CSR build + normalization
    k_probe<<<1, 32>>>(ei);
    k_init<<<(NN + TB - 1) / TB, TB>>>();
    k_deg<<<(EE + TB - 1) / TB, TB>>>(ei, ew);
    k_inv<<<(NN + TB - 1) / TB, TB>>>();
    k_scan<<<1, 1024>>>();
    k_fill<<<(EE + TB - 1) / TB, TB>>>(ei, ew);

    // layer 1: h1 = x @ W1 ; CSR-gather aggregate (+self-loop +bias) -> xemb
    k_gemm<IND, HIDD, 8, false, 1><<<(NN + 63) / 64, TB>>>(x, W1);
    k_agg1<<<(NN * 32 + TB - 1) / TB, TB>>>(xemb, b1);

    // layer 2: h2 = relu(xemb) @ W2 ; aggregate -> out
    k_gemm<HIDD, OUTD, 2, true, 2><<<(NN + 63) / 64, TB>>>(xemb, W2);
    k_agg2<<<(NN * 32 + TB - 1) / TB, TB>>>(outp, b2);
}

// round 10
// speedup vs baseline: 1.2317x; 1.2317x over previous
#include <cuda_runtime.h>
#include <cstdint>

// Problem constants
constexpr int NN   = 100000;   // nodes
constexpr int EE   = 1600000;  // edges
constexpr int IND  = 256;
constexpr int HIDD = 128;
constexpr int OUTD = 32;

// Scratch (static device arrays; no allocation allowed)
__device__ int   g_is32;           // 1 if edge_index is int32, 0 if int64
__device__ float g_deg[NN];        // weighted degree (with self-loop)
__device__ int   g_cnt[NN];        // in-edge count per dst (no self-loop)
__device__ int   g_off[NN];        // CSR row offsets (exclusive prefix of cnt)
__device__ int   g_cur[NN];        // fill cursors
__device__ float g_inv[NN];        // deg^{-1/2}
__device__ int2  g_edge[EE];       // CSR: {src, __float_as_int(norm)} per slot
__device__ float g_h1[(size_t)NN * HIDD];   // x @ W1
__device__ float g_h2[(size_t)NN * OUTD];   // relu(x_emb) @ W2

// ---------------------------------------------------------------------------
// dtype probe: true int64 edge_index values all lie in [0, NN); int32 data
// read as int64 fuses two indices -> huge values. 16 probes => misdetect ~0.
// ---------------------------------------------------------------------------
__global__ void k_probe(const long long* __restrict__ ei) {
    if (threadIdx.x == 0 && blockIdx.x == 0) {
        int ok = 1;
        for (int i = 0; i < 16; i++) {
            long long v = ei[i];
            if (v < 0 || v >= NN) { ok = 0; break; }
        }
        g_is32 = ok ? 0 : 1;
    }
}

__device__ __forceinline__ int load_idx(const long long* ei, size_t pos, int is32) {
    return is32 ? ((const int*)ei)[pos] : (int)ei[pos];
}

// ---------------------------------------------------------------------------
__global__ void k_init() {
    int i = blockIdx.x * blockDim.x + threadIdx.x;
    if (i < NN) { g_deg[i] = 1.0f; g_cnt[i] = 0; }
}

// weighted degree + in-edge counts (scalar atomics only, guarded indices)
__global__ void k_deg(const long long* __restrict__ ei, const float* __restrict__ ew) {
    int e = blockIdx.x * blockDim.x + threadIdx.x;
    if (e < EE) {
        int is32 = g_is32;
        int d = load_idx(ei, (size_t)EE + e, is32);
        if ((unsigned)d < (unsigned)NN) {
            atomicAdd(&g_deg[d], ew[e]);
            atomicAdd(&g_cnt[d], 1);
        }
    }
}

__global__ void k_inv() {
    int i = blockIdx.x * blockDim.x + threadIdx.x;
    if (i < NN) {
        float d = g_deg[i];
        g_inv[i] = d > 0.0f ? rsqrtf(fmaxf(d, 1e-12f)) : 0.0f;
    }
}

// single-block exclusive scan of g_cnt -> g_off (and cursor copy)
__global__ void k_scan() {
    __shared__ int sums[1024];
    const int T  = 1024;
    const int CH = (NN + T - 1) / T;      // 98
    int t  = threadIdx.x;
    int lo = t * CH;
    int hi = lo + CH < NN ? lo + CH : NN;
    int s = 0;
    for (int i = lo; i < hi; i++) s += g_cnt[i];
    sums[t] = s;
    __syncthreads();
    if (t == 0) {
        int run = 0;
        for (int i = 0; i < T; i++) { int v = sums[i]; sums[i] = run; run += v; }
    }
    __syncthreads();
    int run = sums[t];
    for (int i = lo; i < hi; i++) {
        g_off[i] = run;
        g_cur[i] = run;
        run += g_cnt[i];
    }
}

// scatter edges into CSR slots; one packed 8B store per edge
__global__ void k_fill(const long long* __restrict__ ei, const float* __restrict__ ew) {
    int e = blockIdx.x * blockDim.x + threadIdx.x;
    if (e < EE) {
        int is32 = g_is32;
        int s = load_idx(ei, (size_t)e, is32);
        int d = load_idx(ei, (size_t)EE + e, is32);
        if ((unsigned)s < (unsigned)NN && (unsigned)d < (unsigned)NN) {
            int pos = atomicAdd(&g_cur[d], 1);
            float nw = g_inv[s] * ew[e] * g_inv[d];
            g_edge[pos] = make_int2(s, __float_as_int(nw));
        }
    }
}

// ---------------------------------------------------------------------------
// Tiled fp32 GEMM: H[M, BN] = op(X)[M, KK] @ W[KK, BN]
// 256 threads. BM=128 rows. Thread grid TX x TY with TX = BN/TN, TY = 256/TX.
// Micro-tile TM x TN chosen so FMA:LDS-byte ratio ~1 (gemm1: 8x8).
// Invariants: BN % TN == 0; 256 % (BN/TN) == 0; (256/(BN/TN)) * TM == 128;
// TM % 4 == 0; TN % 4 == 0. Both instantiations below satisfy these.
// DSTBUF: 1 -> g_h1, 2 -> g_h2
// ---------------------------------------------------------------------------
template <int KK, int BN, int TM, int TN, bool RELU, int DSTBUF>
__global__ void k_gemm(const float* __restrict__ X, const float* __restrict__ W) {
    float* __restrict__ H = (DSTBUF == 1) ? g_h1 : g_h2;

    constexpr int KT = 16;
    constexpr int BM = 128;
    constexpr int TX = BN / TN;          // 16 (gemm1) / 8 (gemm2)
    constexpr int TY = 256 / TX;         // 16 / 32

    __shared__ __align__(16) float As[KT][BM + 4];   // [k][row], padded
    __shared__ __align__(16) float Bs[KT][BN];

    int tid  = threadIdx.x;
    int tx   = tid % TX;
    int ty   = tid / TX;
    int row0 = blockIdx.x * BM;

    float acc[TM][TN];
#pragma unroll
    for (int i = 0; i < TM; i++)
#pragma unroll
        for (int j = 0; j < TN; j++) acc[i][j] = 0.0f;

    for (int k0 = 0; k0 < KK; k0 += KT) {
        // load X tile (BM x KT) transposed into As[k][row]
        constexpr int XF4 = BM * KT / 4;             // 512 float4
#pragma unroll
        for (int l = 0; l < XF4 / 256; l++) {
            int idx = tid + l * 256;
            int r   = idx >> 2;                      // KT/4 = 4 float4 per row
            int kc  = (idx & 3) << 2;
            int gr  = row0 + r;
            float4 v = make_float4(0.f, 0.f, 0.f, 0.f);
            if (gr < NN) v = *(const float4*)(X + (size_t)gr * KK + k0 + kc);
            if (RELU) {
                v.x = fmaxf(v.x, 0.f); v.y = fmaxf(v.y, 0.f);
                v.z = fmaxf(v.z, 0.f); v.w = fmaxf(v.w, 0.f);
            }
            As[kc + 0][r] = v.x; As[kc + 1][r] = v.y;
            As[kc + 2][r] = v.z; As[kc + 3][r] = v.w;
        }
        // load W tile (KT x BN)
        constexpr int WF4 = KT * BN / 4;             // 512 / 128 float4
#pragma unroll
        for (int l = 0; l < (WF4 + 255) / 256; l++) {
            int idx = tid + l * 256;
            if (idx < WF4) {
                int kk = idx / (BN / 4);
                int cc = (idx % (BN / 4)) * 4;
                *(float4*)(&Bs[kk][cc]) = *(const float4*)(W + (size_t)(k0 + kk) * BN + cc);
            }
        }
        __syncthreads();

#pragma unroll
        for (int k = 0; k < KT; k++) {
            float a[TM], b[TN];
#pragma unroll
            for (int i = 0; i < TM / 4; i++)
                *(float4*)(a + 4 * i) = *(const float4*)(&As[k][ty * TM + 4 * i]);
#pragma unroll
            for (int j = 0; j < TN / 4; j++)
                *(float4*)(b + 4 * j) = *(const float4*)(&Bs[k][tx * TN + 4 * j]);
#pragma unroll
            for (int i = 0; i < TM; i++)
#pragma unroll
                for (int j = 0; j < TN; j++) acc[i][j] += a[i] * b[j];
        }
        __syncthreads();
    }

#pragma unroll
    for (int i = 0; i < TM; i++) {
        int gr = row0 + ty * TM + i;
        if (gr < NN) {
#pragma unroll
            for (int j = 0; j < TN / 4; j++) {
                float4 v = make_float4(acc[i][4 * j], acc[i][4 * j + 1],
                                       acc[i][4 * j + 2], acc[i][4 * j + 3]);
                *(float4*)(H + (size_t)gr * BN + tx * TN + 4 * j) = v;
            }
        }
    }
}

// ---------------------------------------------------------------------------
// CSR aggregation, layer 1: one warp per node, lane owns a float4 chunk.
// out = sum_{e in in(n)} norm_e * h1[src_e] + inv(n)^2 * h1[n] + b1
// Pure gathers + one store; no atomics. Edge loop unrolled x4 for MLP.
// ---------------------------------------------------------------------------
__global__ void k_agg1(float* __restrict__ xemb, const float* __restrict__ b1) {
    int warp = (blockIdx.x * blockDim.x + threadIdx.x) >> 5;
    int lane = threadIdx.x & 31;
    if (warp >= NN) return;

    int beg = g_off[warp];
    int cnt = g_cnt[warp];
    float iv = g_inv[warp];
    float inv2 = iv * iv;

    size_t off = (size_t)warp * HIDD + lane * 4;
    float4 h = *(const float4*)(g_h1 + off);
    float4 b = *(const float4*)(b1 + lane * 4);
    float4 acc;
    acc.x = inv2 * h.x + b.x;
    acc.y = inv2 * h.y + b.y;
    acc.z = inv2 * h.z + b.z;
    acc.w = inv2 * h.w + b.w;

    int i = 0;
    for (; i + 4 <= cnt; i += 4) {
        int2 p0 = g_edge[beg + i + 0], p1 = g_edge[beg + i + 1];
        int2 p2 = g_edge[beg + i + 2], p3 = g_edge[beg + i + 3];
        float n0 = __int_as_float(p0.y), n1 = __int_as_float(p1.y);
        float n2 = __int_as_float(p2.y), n3 = __int_as_float(p3.y);
        float4 v0 = *(const float4*)(g_h1 + (size_t)p0.x * HIDD + lane * 4);
        float4 v1 = *(const float4*)(g_h1 + (size_t)p1.x * HIDD + lane * 4);
        float4 v2 = *(const float4*)(g_h1 + (size_t)p2.x * HIDD + lane * 4);
        float4 v3 = *(const float4*)(g_h1 + (size_t)p3.x * HIDD + lane * 4);
        acc.x += n0 * v0.x + n1 * v1.x + n2 * v2.x + n3 * v3.x;
        acc.y += n0 * v0.y + n1 * v1.y + n2 * v2.y + n3 * v3.y;
        acc.z += n0 * v0.z + n1 * v1.z + n2 * v2.z + n3 * v3.z;
        acc.w += n0 * v0.w + n1 * v1.w + n2 * v2.w + n3 * v3.w;
    }
    for (; i < cnt; i++) {
        int2 p = g_edge[beg + i];
        float nw = __int_as_float(p.y);
        float4 v = *(const float4*)(g_h1 + (size_t)p.x * HIDD + lane * 4);
        acc.x += nw * v.x; acc.y += nw * v.y;
        acc.z += nw * v.z; acc.w += nw * v.w;
    }
    *(float4*)(xemb + off) = acc;
}

// layer 2: 32 features -> one float per lane
__global__ void k_agg2(float* __restrict__ outp, const float* __restrict__ b2) {
    int warp = (blockIdx.x * blockDim.x + threadIdx.x) >> 5;
    int lane = threadIdx.x & 31;
    if (warp >= NN) return;

    int beg = g_off[warp];
    int cnt = g_cnt[warp];
    float iv = g_inv[warp];
    float inv2 = iv * iv;

    size_t off = (size_t)warp * OUTD + lane;
    float acc = inv2 * g_h2[off] + b2[lane];

    int i = 0;
    for (; i + 4 <= cnt; i += 4) {
        int2 p0 = g_edge[beg + i + 0], p1 = g_edge[beg + i + 1];
        int2 p2 = g_edge[beg + i + 2], p3 = g_edge[beg + i + 3];
        acc += __int_as_float(p0.y) * g_h2[(size_t)p0.x * OUTD + lane]
             + __int_as_float(p1.y) * g_h2[(size_t)p1.x * OUTD + lane]
             + __int_as_float(p2.y) * g_h2[(size_t)p2.x * OUTD + lane]
             + __int_as_float(p3.y) * g_h2[(size_t)p3.x * OUTD + lane];
    }
    for (; i < cnt; i++) {
        int2 p = g_edge[beg + i];
        acc += __int_as_float(p.y) * g_h2[(size_t)p.x * OUTD + lane];
    }
    outp[off] = acc;
}

// ---------------------------------------------------------------------------
extern "C" void kernel_launch(void* const* d_in, const int* in_sizes, int n_in,
                              void* d_out, int out_size) {
    const float*     x  = (const float*)d_in[0];
    const long long* ei = (const long long*)d_in[1];   // int32 or int64 — probed
    const float*     ew = (const float*)d_in[2];
    const float*     W1 = (const float*)d_in[3];
    const float*     b1 = (const float*)d_in[4];
    const float*     W2 = (const float*)d_in[5];
    const float*     b2 = (const float*)d_in[6];

    float* outp = (float*)d_out;                       // [NN, OUTD]
    float* xemb = outp + (size_t)NN * OUTD;            // [NN, HIDD]

    const int TB = 256;
    // edge dtype probe + CSR build + normalization
    k_probe<<<1, 32>>>(ei);
    k_init<<<(NN + TB - 1) / TB, TB>>>();
    k_deg<<<(EE + TB - 1) / TB, TB>>>(ei, ew);
    k_inv<<<(NN + TB - 1) / TB, TB>>>();
    k_scan<<<1, 1024>>>();
    k_fill<<<(EE + TB - 1) / TB, TB>>>(ei, ew);

    // layer 1: h1 = x @ W1 ; CSR-gather aggregate (+self-loop +bias) -> xemb
    k_gemm<IND, HIDD, 8, 8, false, 1><<<(NN + 127) / 128, TB>>>(x, W1);
    k_agg1<<<(NN * 32 + TB - 1) / TB, TB>>>(xemb, b1);

    // layer 2: h2 = relu(xemb) @ W2 ; aggregate -> out
    k_gemm<HIDD, OUTD, 4, 4, true, 2><<<(NN + 127) / 128, TB>>>(xemb, W2);
    k_agg2<<<(NN * 32 + TB - 1) / TB, TB>>>(outp, b2);
}